// round 1
// baseline (speedup 1.0000x reference)
#include <cuda_runtime.h>
#include <cstdint>

#define D   64
#define TPB 256
#define WROW 68   // padded row stride (68*4 = 272 B, 16B-aligned, bank-conflict-free transpose)

typedef unsigned long long u64;

__device__ __forceinline__ u64 ffma2(u64 a, u64 b, u64 c) {
    u64 d;
    asm("fma.rn.f32x2 %0, %1, %2, %3;" : "=l"(d) : "l"(a), "l"(b), "l"(c));
    return d;
}
__device__ __forceinline__ u64 splat2(float x) {
    u64 r;
    asm("mov.b64 %0, {%1, %1};" : "=l"(r) : "f"(x));
    return r;
}
__device__ __forceinline__ void unpack2(u64 v, float& lo, float& hi) {
    asm("mov.b64 {%0, %1}, %2;" : "=f"(lo), "=f"(hi) : "l"(v));
}

__global__ void __launch_bounds__(TPB, 1)
chain_kernel(const float* __restrict__ x, const float* __restrict__ W,
             const float* __restrict__ B, float* __restrict__ out,
             int ntok, int nl)
{
    // Double-buffered transposed weights: Wt[buf][k][d] = W[l][d][k]
    __shared__ __align__(16) float Wt[2][D][WROW];
    __shared__ __align__(16) float bs[2][D];

    const int tid = threadIdx.x;
    int token = blockIdx.x * TPB + tid;
    const bool active = token < ntok;
    const int tok = active ? token : (ntok - 1);

    // Load this thread's token activation into registers (16 x LDG.128)
    float h[D];
    {
        const float4* xin = (const float4*)(x + (size_t)tok * D);
#pragma unroll
        for (int i = 0; i < D / 4; i++) {
            float4 v = xin[i];
            h[4*i+0] = v.x; h[4*i+1] = v.y; h[4*i+2] = v.z; h[4*i+3] = v.w;
        }
    }

    // Weight-loader assignment: thread -> (row d, 16-wide k chunk)
    const int ld_d  = tid & (D - 1);
    const int ld_kc = (tid >> 6) * 16;   // 256 threads -> 4 chunks of 16

    // Prefetch layer 0
    {
        const float4* src = (const float4*)(W + (size_t)ld_d * D + ld_kc);
        float4 v0 = src[0], v1 = src[1], v2 = src[2], v3 = src[3];
        float t16[16] = { v0.x, v0.y, v0.z, v0.w,  v1.x, v1.y, v1.z, v1.w,
                          v2.x, v2.y, v2.z, v2.w,  v3.x, v3.y, v3.z, v3.w };
#pragma unroll
        for (int j = 0; j < 16; j++) Wt[0][ld_kc + j][ld_d] = t16[j];
        if (tid < D) bs[0][tid] = B[tid];
    }
    __syncthreads();

    for (int l = 0; l < nl; l++) {
        const int cur = l & 1;
        const int nxt = cur ^ 1;

        // Prefetch next layer's weights into the other buffer (overlaps compute)
        if (l + 1 < nl) {
            const float4* src = (const float4*)(W + (size_t)(l + 1) * D * D
                                                  + (size_t)ld_d * D + ld_kc);
            float4 v0 = src[0], v1 = src[1], v2 = src[2], v3 = src[3];
            float t16[16] = { v0.x, v0.y, v0.z, v0.w,  v1.x, v1.y, v1.z, v1.w,
                              v2.x, v2.y, v2.z, v2.w,  v3.x, v3.y, v3.z, v3.w };
#pragma unroll
            for (int j = 0; j < 16; j++) Wt[nxt][ld_kc + j][ld_d] = t16[j];
            if (tid < D) bs[nxt][tid] = B[(size_t)(l + 1) * D + tid];
        }

        // y[d] = b[d] + sum_k h[k] * W[d][k], packed 2 output features per u64
        u64 y[D / 2];
        {
            const u64* bp = (const u64*)bs[cur];
#pragma unroll
            for (int i = 0; i < D / 2; i++) y[i] = bp[i];
        }

#pragma unroll
        for (int k = 0; k < D; k++) {
            const u64 hk2 = splat2(h[k]);
            const ulonglong2* wrow = (const ulonglong2*)Wt[cur][k];  // broadcast reads
#pragma unroll
            for (int i = 0; i < D / 4; i++) {
                ulonglong2 wv = wrow[i];        // LDS.128 -> two packed f32x2 multipliers
                y[2*i + 0] = ffma2(hk2, wv.x, y[2*i + 0]);
                y[2*i + 1] = ffma2(hk2, wv.y, y[2*i + 1]);
            }
        }

#pragma unroll
        for (int i = 0; i < D / 2; i++) unpack2(y[i], h[2*i], h[2*i + 1]);

        __syncthreads();   // buffer `cur` free for overwrite; buffer `nxt` complete
    }

    if (active) {
        float4* dst = (float4*)(out + (size_t)tok * D);
#pragma unroll
        for (int i = 0; i < D / 4; i++) {
            float4 v;
            v.x = h[4*i+0]; v.y = h[4*i+1]; v.z = h[4*i+2]; v.w = h[4*i+3];
            dst[i] = v;
        }
    }
}

extern "C" void kernel_launch(void* const* d_in, const int* in_sizes, int n_in,
                              void* d_out, int out_size)
{
    const float* x = (const float*)d_in[0];
    const float* W = (const float*)d_in[1];
    const float* B = (const float*)d_in[2];
    float* out = (float*)d_out;

    const int ntok = in_sizes[0] / D;            // 524288
    const int nl   = in_sizes[1] / (D * D);      // 20
    const int grid = (ntok + TPB - 1) / TPB;     // 2048

    chain_kernel<<<grid, TPB>>>(x, W, B, out, ntok, nl);
}

// round 3
// speedup vs baseline: 3.6229x; 3.6229x over previous
#include <cuda_runtime.h>
#include <cuda_bf16.h>
#include <cstdint>

#define NTHREADS 256   // 8 warps, 32 tokens/warp -> 256 tokens per CTA

static __device__ __forceinline__ uint32_t s2u(const void* p) {
    uint32_t a;
    asm("{ .reg .u64 t; cvta.to.shared.u64 t, %1; cvt.u32.u64 %0, t; }"
        : "=r"(a) : "l"(p));
    return a;
}

static __device__ __forceinline__ void ldsm4(uint32_t& r0, uint32_t& r1,
                                             uint32_t& r2, uint32_t& r3, uint32_t a) {
    asm volatile("ldmatrix.sync.aligned.m8n8.x4.shared.b16 {%0,%1,%2,%3}, [%4];"
                 : "=r"(r0), "=r"(r1), "=r"(r2), "=r"(r3) : "r"(a));
}

static __device__ __forceinline__ void mma16816(float* c, const uint32_t* a,
                                                uint32_t b0, uint32_t b1) {
    asm volatile("mma.sync.aligned.m16n8k16.row.col.f32.bf16.bf16.f32 "
                 "{%0,%1,%2,%3}, {%4,%5,%6,%7}, {%8,%9}, {%0,%1,%2,%3};"
                 : "+f"(c[0]), "+f"(c[1]), "+f"(c[2]), "+f"(c[3])
                 : "r"(a[0]), "r"(a[1]), "r"(a[2]), "r"(a[3]), "r"(b0), "r"(b1));
}

// split (a,b) fp32 pair -> packed bf16x2 hi + packed bf16x2 lo (lo = exact residual)
static __device__ __forceinline__ void split2(float a, float b, uint32_t& hi, uint32_t& lo) {
    uint32_t h, l;
    asm("cvt.rn.bf16x2.f32 %0, %1, %2;" : "=r"(h) : "f"(b), "f"(a)); // lo-half=a, hi-half=b
    float ha = __uint_as_float(h << 16);
    float hb = __uint_as_float(h & 0xFFFF0000u);
    float la = a - ha;
    float lb = b - hb;
    asm("cvt.rn.bf16x2.f32 %0, %1, %2;" : "=r"(l) : "f"(lb), "f"(la));
    hi = h; lo = l;
}

__global__ void __launch_bounds__(NTHREADS, 1)
chain_hmma(const float* __restrict__ x, const float* __restrict__ W,
           const float* __restrict__ Bv, float* __restrict__ out, int nl)
{
    // double-buffered bf16 weights (row n, col k), 128B rows, SW128 xor swizzle
    __shared__ __align__(128) __nv_bfloat16 Whi[2][64 * 64];
    __shared__ __align__(128) __nv_bfloat16 Wlo[2][64 * 64];
    __shared__ float biasS[2][64];

    const int tid  = threadIdx.x;
    const int lane = tid & 31;
    const int warp = tid >> 5;
    const int gid  = lane >> 2;     // MMA groupID (row within tile)
    const int tig  = lane & 3;      // thread-in-group

    // weight-converter assignment: 16 consecutive floats of one row
    const int wn = tid >> 2;
    const int wk = (tid & 3) * 16;
    const uint32_t wxor = ((uint32_t)(wn & 7)) << 4;
    const uint32_t woff0 = (uint32_t)wn * 128 + (uint32_t)(tid & 3) * 32;
    const uint32_t wsw0 = woff0 ^ wxor;
    const uint32_t wsw1 = (woff0 + 16) ^ wxor;

    // ldmatrix per-thread address pieces: row = np*16 + (lane&15), kbyte = kt*32 + 16*(lane>>4)
    const uint32_t rowoff = (uint32_t)(lane & 15) * 128;
    uint32_t kx[4];
#pragma unroll
    for (int kt = 0; kt < 4; kt++)
        kx[kt] = ((uint32_t)(kt * 32 + ((lane >> 4) << 4))) ^ ((uint32_t)(lane & 7) << 4);

    const size_t wtok = (size_t)blockIdx.x * 256 + (size_t)warp * 32;

    float    C[2][8][4];            // [mtile][ntile][frag]
    uint32_t Ahi[2][4][4], Alo[2][4][4];  // [mtile][ktile][frag]

#pragma unroll
    for (int mt = 0; mt < 2; mt++)
#pragma unroll
        for (int nt = 0; nt < 8; nt++)
#pragma unroll
            for (int i = 0; i < 4; i++) C[mt][nt][i] = 0.f;

    // ---- bootstrap: load x directly into A-fragment layout, split hi/lo ----
#pragma unroll
    for (int mt = 0; mt < 2; mt++) {
#pragma unroll
        for (int kt = 0; kt < 4; kt++) {
            const float* p = x + (wtok + mt * 16 + gid) * 64 + kt * 16 + 2 * tig;
            float2 v0 = *(const float2*)p;              // (r,   k0..1)
            float2 v1 = *(const float2*)(p + 8 * 64);   // (r+8, k0..1)
            float2 v2 = *(const float2*)(p + 8);        // (r,   k8..9)
            float2 v3 = *(const float2*)(p + 8 * 64 + 8);
            split2(v0.x, v0.y, Ahi[mt][kt][0], Alo[mt][kt][0]);
            split2(v1.x, v1.y, Ahi[mt][kt][1], Alo[mt][kt][1]);
            split2(v2.x, v2.y, Ahi[mt][kt][2], Alo[mt][kt][2]);
            split2(v3.x, v3.y, Ahi[mt][kt][3], Alo[mt][kt][3]);
        }
    }

    // ---- layer-0 weights + bias into buffer 0 ----
    {
        const float4* ws = (const float4*)(W + (size_t)wn * 64 + wk);
        float4 w0 = ws[0], w1 = ws[1], w2 = ws[2], w3 = ws[3];
        uint32_t hi[8], lo[8];
        split2(w0.x, w0.y, hi[0], lo[0]); split2(w0.z, w0.w, hi[1], lo[1]);
        split2(w1.x, w1.y, hi[2], lo[2]); split2(w1.z, w1.w, hi[3], lo[3]);
        split2(w2.x, w2.y, hi[4], lo[4]); split2(w2.z, w2.w, hi[5], lo[5]);
        split2(w3.x, w3.y, hi[6], lo[6]); split2(w3.z, w3.w, hi[7], lo[7]);
        char* bh = (char*)&Whi[0][0];
        char* bl = (char*)&Wlo[0][0];
        *(uint4*)(bh + wsw0) = make_uint4(hi[0], hi[1], hi[2], hi[3]);
        *(uint4*)(bh + wsw1) = make_uint4(hi[4], hi[5], hi[6], hi[7]);
        *(uint4*)(bl + wsw0) = make_uint4(lo[0], lo[1], lo[2], lo[3]);
        *(uint4*)(bl + wsw1) = make_uint4(lo[4], lo[5], lo[6], lo[7]);
        if (tid < 64) biasS[0][tid] = Bv[tid];
    }
    __syncthreads();

    for (int l = 0; l < nl; l++) {
        const int buf = l & 1;

        // stage next layer's weights/bias in registers (LDG overlaps MMA loop)
        float4 w0, w1, w2, w3;
        float bnx = 0.f;
        const bool more = (l + 1 < nl);
        if (more) {
            const float4* ws = (const float4*)(W + (size_t)(l + 1) * 4096
                                                 + (size_t)wn * 64 + wk);
            w0 = ws[0]; w1 = ws[1]; w2 = ws[2]; w3 = ws[3];
            if (tid < 64) bnx = Bv[(size_t)(l + 1) * 64 + tid];
        }

        const uint32_t hBase = s2u(&Whi[buf][0]) + rowoff;
        const uint32_t lBase = s2u(&Wlo[buf][0]) + rowoff;

#pragma unroll
        for (int np = 0; np < 4; np++) {
#pragma unroll
            for (int kt = 0; kt < 4; kt++) {
                uint32_t b0, b1, b2, b3;
                ldsm4(b0, b1, b2, b3, hBase + np * 2048 + kx[kt]);
                mma16816(C[0][2*np],   Ahi[0][kt], b0, b2);
                mma16816(C[1][2*np],   Ahi[1][kt], b0, b2);
                mma16816(C[0][2*np+1], Ahi[0][kt], b1, b3);
                mma16816(C[1][2*np+1], Ahi[1][kt], b1, b3);
                mma16816(C[0][2*np],   Alo[0][kt], b0, b2);
                mma16816(C[1][2*np],   Alo[1][kt], b0, b2);
                mma16816(C[0][2*np+1], Alo[0][kt], b1, b3);
                mma16816(C[1][2*np+1], Alo[1][kt], b1, b3);
                uint32_t q0, q1, q2, q3;
                ldsm4(q0, q1, q2, q3, lBase + np * 2048 + kx[kt]);
                mma16816(C[0][2*np],   Ahi[0][kt], q0, q2);
                mma16816(C[1][2*np],   Ahi[1][kt], q0, q2);
                mma16816(C[0][2*np+1], Ahi[0][kt], q1, q3);
                mma16816(C[1][2*np+1], Ahi[1][kt], q1, q3);
            }
        }

        // bias add
        float2 bb[8];
#pragma unroll
        for (int nt = 0; nt < 8; nt++)
            bb[nt] = *(const float2*)&biasS[buf][nt * 8 + 2 * tig];
#pragma unroll
        for (int mt = 0; mt < 2; mt++)
#pragma unroll
            for (int nt = 0; nt < 8; nt++) {
                C[mt][nt][0] += bb[nt].x; C[mt][nt][1] += bb[nt].y;
                C[mt][nt][2] += bb[nt].x; C[mt][nt][3] += bb[nt].y;
            }

        if (!more) {
            // final layer: store fp32 result
#pragma unroll
            for (int mt = 0; mt < 2; mt++) {
                size_t r = wtok + mt * 16 + gid;
#pragma unroll
                for (int nt = 0; nt < 8; nt++) {
                    int col = nt * 8 + 2 * tig;
                    *(float2*)(out + r * 64 + col) =
                        make_float2(C[mt][nt][0], C[mt][nt][1]);
                    *(float2*)(out + (r + 8) * 64 + col) =
                        make_float2(C[mt][nt][2], C[mt][nt][3]);
                }
            }
        } else {
            // C-fragment (two n8 tiles) -> next layer's A-fragment (one k16 tile)
#pragma unroll
            for (int mt = 0; mt < 2; mt++)
#pragma unroll
                for (int kt = 0; kt < 4; kt++) {
                    split2(C[mt][2*kt][0],   C[mt][2*kt][1],   Ahi[mt][kt][0], Alo[mt][kt][0]);
                    split2(C[mt][2*kt][2],   C[mt][2*kt][3],   Ahi[mt][kt][1], Alo[mt][kt][1]);
                    split2(C[mt][2*kt+1][0], C[mt][2*kt+1][1], Ahi[mt][kt][2], Alo[mt][kt][2]);
                    split2(C[mt][2*kt+1][2], C[mt][2*kt+1][3], Ahi[mt][kt][3], Alo[mt][kt][3]);
                }
#pragma unroll
            for (int mt = 0; mt < 2; mt++)
#pragma unroll
                for (int nt = 0; nt < 8; nt++)
#pragma unroll
                    for (int i = 0; i < 4; i++) C[mt][nt][i] = 0.f;

            // write staged weights into the other buffer
            uint32_t hi[8], lo[8];
            split2(w0.x, w0.y, hi[0], lo[0]); split2(w0.z, w0.w, hi[1], lo[1]);
            split2(w1.x, w1.y, hi[2], lo[2]); split2(w1.z, w1.w, hi[3], lo[3]);
            split2(w2.x, w2.y, hi[4], lo[4]); split2(w2.z, w2.w, hi[5], lo[5]);
            split2(w3.x, w3.y, hi[6], lo[6]); split2(w3.z, w3.w, hi[7], lo[7]);
            char* bh = (char*)&Whi[buf ^ 1][0];
            char* bl = (char*)&Wlo[buf ^ 1][0];
            *(uint4*)(bh + wsw0) = make_uint4(hi[0], hi[1], hi[2], hi[3]);
            *(uint4*)(bh + wsw1) = make_uint4(hi[4], hi[5], hi[6], hi[7]);
            *(uint4*)(bl + wsw0) = make_uint4(lo[0], lo[1], lo[2], lo[3]);
            *(uint4*)(bl + wsw1) = make_uint4(lo[4], lo[5], lo[6], lo[7]);
            if (tid < 64) biasS[buf ^ 1][tid] = bnx;

            __syncthreads();
        }
    }
}

extern "C" void kernel_launch(void* const* d_in, const int* in_sizes, int n_in,
                              void* d_out, int out_size)
{
    const float* x  = (const float*)d_in[0];
    const float* W  = (const float*)d_in[1];
    const float* Bv = (const float*)d_in[2];
    float* out = (float*)d_out;

    const int ntok = in_sizes[0] / 64;        // 524288
    const int nl   = in_sizes[1] / (64 * 64); // 20
    const int grid = ntok / 256;              // 2048

    chain_hmma<<<grid, NTHREADS>>>(x, W, Bv, out, nl);
}

// round 4
// speedup vs baseline: 14.3453x; 3.9596x over previous
#include <cuda_runtime.h>
#include <cuda_bf16.h>
#include <cstdint>

// ---------------- scratch (static device globals: no allocs) ----------------
__device__ float g_R[256 * 64];   // chain output on [I; 0] probe rows
__device__ float g_W[64 * 64];    // effective weight, [n][k] layout
__device__ float g_c[64];         // effective bias

// ---------------- common helpers ----------------
static __device__ __forceinline__ uint32_t s2u(const void* p) {
    uint32_t a;
    asm("{ .reg .u64 t; cvta.to.shared.u64 t, %1; cvt.u32.u64 %0, t; }"
        : "=r"(a) : "l"(p));
    return a;
}

static __device__ __forceinline__ void ldsm4(uint32_t& r0, uint32_t& r1,
                                             uint32_t& r2, uint32_t& r3, uint32_t a) {
    asm volatile("ldmatrix.sync.aligned.m8n8.x4.shared.b16 {%0,%1,%2,%3}, [%4];"
                 : "=r"(r0), "=r"(r1), "=r"(r2), "=r"(r3) : "r"(a));
}

static __device__ __forceinline__ void mma16816(float* c, const uint32_t* a,
                                                uint32_t b0, uint32_t b1) {
    asm volatile("mma.sync.aligned.m16n8k16.row.col.f32.bf16.bf16.f32 "
                 "{%0,%1,%2,%3}, {%4,%5,%6,%7}, {%8,%9}, {%0,%1,%2,%3};"
                 : "+f"(c[0]), "+f"(c[1]), "+f"(c[2]), "+f"(c[3])
                 : "r"(a[0]), "r"(a[1]), "r"(a[2]), "r"(a[3]), "r"(b0), "r"(b1));
}

// split (a,b) fp32 pair -> packed bf16x2 hi + packed bf16x2 lo (exact residual)
static __device__ __forceinline__ void split2(float a, float b, uint32_t& hi, uint32_t& lo) {
    uint32_t h, l;
    asm("cvt.rn.bf16x2.f32 %0, %1, %2;" : "=r"(h) : "f"(b), "f"(a));
    float ha = __uint_as_float(h << 16);
    float hb = __uint_as_float(h & 0xFFFF0000u);
    float la = a - ha;
    float lb = b - hb;
    asm("cvt.rn.bf16x2.f32 %0, %1, %2;" : "=r"(l) : "f"(lb), "f"(la));
    hi = h; lo = l;
}

// ============================================================================
// Kernel 1: run the 20-layer chain on probe rows [I(64); 0(192)] -> g_R.
// Row k<64 gives M_k + c; row 64 gives c.  (Single CTA, 8 warps.)
// ============================================================================
__global__ void __launch_bounds__(256, 1)
chain_build(const float* __restrict__ W, const float* __restrict__ Bv, int nl)
{
    __shared__ __align__(128) __nv_bfloat16 Whi[2][64 * 64];
    __shared__ __align__(128) __nv_bfloat16 Wlo[2][64 * 64];
    __shared__ float biasS[2][64];

    const int tid  = threadIdx.x;
    const int lane = tid & 31;
    const int warp = tid >> 5;
    const int gid  = lane >> 2;
    const int tig  = lane & 3;

    const int wn = tid >> 2;
    const int wk = (tid & 3) * 16;
    const uint32_t wxor  = ((uint32_t)(wn & 7)) << 4;
    const uint32_t woff0 = (uint32_t)wn * 128 + (uint32_t)(tid & 3) * 32;
    const uint32_t wsw0  = woff0 ^ wxor;
    const uint32_t wsw1  = (woff0 + 16) ^ wxor;

    const uint32_t rowoff = (uint32_t)(lane & 15) * 128;
    uint32_t kx[4];
#pragma unroll
    for (int kt = 0; kt < 4; kt++)
        kx[kt] = ((uint32_t)(kt * 32 + ((lane >> 4) << 4))) ^ ((uint32_t)(lane & 7) << 4);

    const int wtok = warp * 32;

    float    C[2][8][4];
    uint32_t Ahi[2][4][4], Alo[2][4][4];

#pragma unroll
    for (int mt = 0; mt < 2; mt++)
#pragma unroll
        for (int nt = 0; nt < 8; nt++)
#pragma unroll
            for (int i = 0; i < 4; i++) C[mt][nt][i] = 0.f;

    // bootstrap: synthesized identity probe (rows<64: e_row; rows>=64: 0)
#pragma unroll
    for (int mt = 0; mt < 2; mt++) {
#pragma unroll
        for (int kt = 0; kt < 4; kt++) {
            int row  = wtok + mt * 16 + gid;
            int bk   = kt * 16 + 2 * tig;
            float v0x = (row     == bk    ) ? 1.f : 0.f;
            float v0y = (row     == bk + 1) ? 1.f : 0.f;
            float v1x = (row + 8 == bk    ) ? 1.f : 0.f;
            float v1y = (row + 8 == bk + 1) ? 1.f : 0.f;
            float v2x = (row     == bk + 8) ? 1.f : 0.f;
            float v2y = (row     == bk + 9) ? 1.f : 0.f;
            float v3x = (row + 8 == bk + 8) ? 1.f : 0.f;
            float v3y = (row + 8 == bk + 9) ? 1.f : 0.f;
            split2(v0x, v0y, Ahi[mt][kt][0], Alo[mt][kt][0]);
            split2(v1x, v1y, Ahi[mt][kt][1], Alo[mt][kt][1]);
            split2(v2x, v2y, Ahi[mt][kt][2], Alo[mt][kt][2]);
            split2(v3x, v3y, Ahi[mt][kt][3], Alo[mt][kt][3]);
        }
    }

    // layer-0 weights + bias
    {
        const float4* ws = (const float4*)(W + (size_t)wn * 64 + wk);
        float4 w0 = ws[0], w1 = ws[1], w2 = ws[2], w3 = ws[3];
        uint32_t hi[8], lo[8];
        split2(w0.x, w0.y, hi[0], lo[0]); split2(w0.z, w0.w, hi[1], lo[1]);
        split2(w1.x, w1.y, hi[2], lo[2]); split2(w1.z, w1.w, hi[3], lo[3]);
        split2(w2.x, w2.y, hi[4], lo[4]); split2(w2.z, w2.w, hi[5], lo[5]);
        split2(w3.x, w3.y, hi[6], lo[6]); split2(w3.z, w3.w, hi[7], lo[7]);
        char* bh = (char*)&Whi[0][0];
        char* bl = (char*)&Wlo[0][0];
        *(uint4*)(bh + wsw0) = make_uint4(hi[0], hi[1], hi[2], hi[3]);
        *(uint4*)(bh + wsw1) = make_uint4(hi[4], hi[5], hi[6], hi[7]);
        *(uint4*)(bl + wsw0) = make_uint4(lo[0], lo[1], lo[2], lo[3]);
        *(uint4*)(bl + wsw1) = make_uint4(lo[4], lo[5], lo[6], lo[7]);
        if (tid < 64) biasS[0][tid] = Bv[tid];
    }
    __syncthreads();

    for (int l = 0; l < nl; l++) {
        const int buf = l & 1;
        float4 w0, w1, w2, w3;
        float bnx = 0.f;
        const bool more = (l + 1 < nl);
        if (more) {
            const float4* ws = (const float4*)(W + (size_t)(l + 1) * 4096
                                                 + (size_t)wn * 64 + wk);
            w0 = ws[0]; w1 = ws[1]; w2 = ws[2]; w3 = ws[3];
            if (tid < 64) bnx = Bv[(size_t)(l + 1) * 64 + tid];
        }

        const uint32_t hBase = s2u(&Whi[buf][0]) + rowoff;
        const uint32_t lBase = s2u(&Wlo[buf][0]) + rowoff;

#pragma unroll
        for (int np = 0; np < 4; np++) {
#pragma unroll
            for (int kt = 0; kt < 4; kt++) {
                uint32_t b0, b1, b2, b3;
                ldsm4(b0, b1, b2, b3, hBase + np * 2048 + kx[kt]);
                mma16816(C[0][2*np],   Ahi[0][kt], b0, b2);
                mma16816(C[1][2*np],   Ahi[1][kt], b0, b2);
                mma16816(C[0][2*np+1], Ahi[0][kt], b1, b3);
                mma16816(C[1][2*np+1], Ahi[1][kt], b1, b3);
                mma16816(C[0][2*np],   Alo[0][kt], b0, b2);
                mma16816(C[1][2*np],   Alo[1][kt], b0, b2);
                mma16816(C[0][2*np+1], Alo[0][kt], b1, b3);
                mma16816(C[1][2*np+1], Alo[1][kt], b1, b3);
                uint32_t q0, q1, q2, q3;
                ldsm4(q0, q1, q2, q3, lBase + np * 2048 + kx[kt]);
                mma16816(C[0][2*np],   Ahi[0][kt], q0, q2);
                mma16816(C[1][2*np],   Ahi[1][kt], q0, q2);
                mma16816(C[0][2*np+1], Ahi[0][kt], q1, q3);
                mma16816(C[1][2*np+1], Ahi[1][kt], q1, q3);
            }
        }

        float2 bb[8];
#pragma unroll
        for (int nt = 0; nt < 8; nt++)
            bb[nt] = *(const float2*)&biasS[buf][nt * 8 + 2 * tig];
#pragma unroll
        for (int mt = 0; mt < 2; mt++)
#pragma unroll
            for (int nt = 0; nt < 8; nt++) {
                C[mt][nt][0] += bb[nt].x; C[mt][nt][1] += bb[nt].y;
                C[mt][nt][2] += bb[nt].x; C[mt][nt][3] += bb[nt].y;
            }

        if (!more) {
#pragma unroll
            for (int mt = 0; mt < 2; mt++) {
                int r = wtok + mt * 16 + gid;
#pragma unroll
                for (int nt = 0; nt < 8; nt++) {
                    int col = nt * 8 + 2 * tig;
                    *(float2*)(g_R + r * 64 + col) =
                        make_float2(C[mt][nt][0], C[mt][nt][1]);
                    *(float2*)(g_R + (r + 8) * 64 + col) =
                        make_float2(C[mt][nt][2], C[mt][nt][3]);
                }
            }
        } else {
#pragma unroll
            for (int mt = 0; mt < 2; mt++)
#pragma unroll
                for (int kt = 0; kt < 4; kt++) {
                    split2(C[mt][2*kt][0],   C[mt][2*kt][1],   Ahi[mt][kt][0], Alo[mt][kt][0]);
                    split2(C[mt][2*kt][2],   C[mt][2*kt][3],   Ahi[mt][kt][1], Alo[mt][kt][1]);
                    split2(C[mt][2*kt+1][0], C[mt][2*kt+1][1], Ahi[mt][kt][2], Alo[mt][kt][2]);
                    split2(C[mt][2*kt+1][2], C[mt][2*kt+1][3], Ahi[mt][kt][3], Alo[mt][kt][3]);
                }
#pragma unroll
            for (int mt = 0; mt < 2; mt++)
#pragma unroll
                for (int nt = 0; nt < 8; nt++)
#pragma unroll
                    for (int i = 0; i < 4; i++) C[mt][nt][i] = 0.f;

            uint32_t hi[8], lo[8];
            split2(w0.x, w0.y, hi[0], lo[0]); split2(w0.z, w0.w, hi[1], lo[1]);
            split2(w1.x, w1.y, hi[2], lo[2]); split2(w1.z, w1.w, hi[3], lo[3]);
            split2(w2.x, w2.y, hi[4], lo[4]); split2(w2.z, w2.w, hi[5], lo[5]);
            split2(w3.x, w3.y, hi[6], lo[6]); split2(w3.z, w3.w, hi[7], lo[7]);
            char* bh = (char*)&Whi[buf ^ 1][0];
            char* bl = (char*)&Wlo[buf ^ 1][0];
            *(uint4*)(bh + wsw0) = make_uint4(hi[0], hi[1], hi[2], hi[3]);
            *(uint4*)(bh + wsw1) = make_uint4(hi[4], hi[5], hi[6], hi[7]);
            *(uint4*)(bl + wsw0) = make_uint4(lo[0], lo[1], lo[2], lo[3]);
            *(uint4*)(bl + wsw1) = make_uint4(lo[4], lo[5], lo[6], lo[7]);
            if (tid < 64) biasS[buf ^ 1][tid] = bnx;

            __syncthreads();
        }
    }
}

// ============================================================================
// Kernel 2: Weff[n][k] = R[k][n] - R[64][n];  c[n] = R[64][n]
// ============================================================================
__global__ void __launch_bounds__(256, 4)
build_eff()
{
    int t = blockIdx.x * 256 + threadIdx.x;   // 0..4095
    int n = t >> 6;
    int k = t & 63;
    g_W[t] = g_R[k * 64 + n] - g_R[64 * 64 + n];
    if (t < 64) g_c[t] = g_R[64 * 64 + t];
}

// ============================================================================
// Kernel 3: y = x @ Weff^T + c  (one 3-term bf16 HMMA layer; memory-bound)
// 128 tokens/CTA, 16 tokens/warp, 2 CTAs/SM.
// ============================================================================
__global__ void __launch_bounds__(256, 2)
apply_affine(const float* __restrict__ x, float* __restrict__ out)
{
    __shared__ __align__(128) __nv_bfloat16 Whi[64 * 64];
    __shared__ __align__(128) __nv_bfloat16 Wlo[64 * 64];
    __shared__ float biasS[64];

    const int tid  = threadIdx.x;
    const int lane = tid & 31;
    const int warp = tid >> 5;
    const int gid  = lane >> 2;
    const int tig  = lane & 3;

    const size_t wtok = (size_t)blockIdx.x * 128 + (size_t)warp * 16;

    // ---- bootstrap x -> A fragments (issue LDGs first) ----
    uint32_t Ahi[4][4], Alo[4][4];
    float2 v0[4], v1[4], v2[4], v3[4];
#pragma unroll
    for (int kt = 0; kt < 4; kt++) {
        const float* p = x + (wtok + gid) * 64 + kt * 16 + 2 * tig;
        v0[kt] = *(const float2*)p;
        v1[kt] = *(const float2*)(p + 8 * 64);
        v2[kt] = *(const float2*)(p + 8);
        v3[kt] = *(const float2*)(p + 8 * 64 + 8);
    }

    // ---- weight conversion: g_W -> bf16 hi/lo smem (SW128 swizzle) ----
    {
        const int wn = tid >> 2;
        const int wk = (tid & 3) * 16;
        const uint32_t wxor  = ((uint32_t)(wn & 7)) << 4;
        const uint32_t woff0 = (uint32_t)wn * 128 + (uint32_t)(tid & 3) * 32;
        const uint32_t wsw0  = woff0 ^ wxor;
        const uint32_t wsw1  = (woff0 + 16) ^ wxor;

        const float4* ws = (const float4*)(g_W + wn * 64 + wk);
        float4 w0 = ws[0], w1 = ws[1], w2 = ws[2], w3 = ws[3];
        uint32_t hi[8], lo[8];
        split2(w0.x, w0.y, hi[0], lo[0]); split2(w0.z, w0.w, hi[1], lo[1]);
        split2(w1.x, w1.y, hi[2], lo[2]); split2(w1.z, w1.w, hi[3], lo[3]);
        split2(w2.x, w2.y, hi[4], lo[4]); split2(w2.z, w2.w, hi[5], lo[5]);
        split2(w3.x, w3.y, hi[6], lo[6]); split2(w3.z, w3.w, hi[7], lo[7]);
        char* bh = (char*)&Whi[0];
        char* bl = (char*)&Wlo[0];
        *(uint4*)(bh + wsw0) = make_uint4(hi[0], hi[1], hi[2], hi[3]);
        *(uint4*)(bh + wsw1) = make_uint4(hi[4], hi[5], hi[6], hi[7]);
        *(uint4*)(bl + wsw0) = make_uint4(lo[0], lo[1], lo[2], lo[3]);
        *(uint4*)(bl + wsw1) = make_uint4(lo[4], lo[5], lo[6], lo[7]);
        if (tid < 64) biasS[tid] = g_c[tid];
    }

#pragma unroll
    for (int kt = 0; kt < 4; kt++) {
        split2(v0[kt].x, v0[kt].y, Ahi[kt][0], Alo[kt][0]);
        split2(v1[kt].x, v1[kt].y, Ahi[kt][1], Alo[kt][1]);
        split2(v2[kt].x, v2[kt].y, Ahi[kt][2], Alo[kt][2]);
        split2(v3[kt].x, v3[kt].y, Ahi[kt][3], Alo[kt][3]);
    }

    float C[8][4];
#pragma unroll
    for (int nt = 0; nt < 8; nt++)
#pragma unroll
        for (int i = 0; i < 4; i++) C[nt][i] = 0.f;

    __syncthreads();

    const uint32_t rowoff = (uint32_t)(lane & 15) * 128;
    uint32_t kx[4];
#pragma unroll
    for (int kt = 0; kt < 4; kt++)
        kx[kt] = ((uint32_t)(kt * 32 + ((lane >> 4) << 4))) ^ ((uint32_t)(lane & 7) << 4);

    const uint32_t hBase = s2u(&Whi[0]) + rowoff;
    const uint32_t lBase = s2u(&Wlo[0]) + rowoff;

#pragma unroll
    for (int kt = 0; kt < 4; kt++) {
#pragma unroll
        for (int np = 0; np < 4; np++) {
            uint32_t b0, b1, b2, b3;
            ldsm4(b0, b1, b2, b3, hBase + np * 2048 + kx[kt]);
            mma16816(C[2*np],   Ahi[kt], b0, b2);
            mma16816(C[2*np+1], Ahi[kt], b1, b3);
            mma16816(C[2*np],   Alo[kt], b0, b2);
            mma16816(C[2*np+1], Alo[kt], b1, b3);
            uint32_t q0, q1, q2, q3;
            ldsm4(q0, q1, q2, q3, lBase + np * 2048 + kx[kt]);
            mma16816(C[2*np],   Ahi[kt], q0, q2);
            mma16816(C[2*np+1], Ahi[kt], q1, q3);
        }
    }

    // bias + store
#pragma unroll
    for (int nt = 0; nt < 8; nt++) {
        float2 bb = *(const float2*)&biasS[nt * 8 + 2 * tig];
        C[nt][0] += bb.x; C[nt][1] += bb.y;
        C[nt][2] += bb.x; C[nt][3] += bb.y;
    }

    size_t r = wtok + gid;
#pragma unroll
    for (int nt = 0; nt < 8; nt++) {
        int col = nt * 8 + 2 * tig;
        *(float2*)(out + r * 64 + col)       = make_float2(C[nt][0], C[nt][1]);
        *(float2*)(out + (r + 8) * 64 + col) = make_float2(C[nt][2], C[nt][3]);
    }
}

extern "C" void kernel_launch(void* const* d_in, const int* in_sizes, int n_in,
                              void* d_out, int out_size)
{
    const float* x  = (const float*)d_in[0];
    const float* W  = (const float*)d_in[1];
    const float* Bv = (const float*)d_in[2];
    float* out = (float*)d_out;

    const int ntok = in_sizes[0] / 64;        // 524288
    const int nl   = in_sizes[1] / (64 * 64); // 20

    chain_build<<<1, 256>>>(W, Bv, nl);
    build_eff<<<16, 256>>>();
    apply_affine<<<ntok / 128, 256>>>(x, out);
}

// round 6
// speedup vs baseline: 16.6355x; 1.1597x over previous
#include <cuda_runtime.h>
#include <cuda_bf16.h>
#include <cstdint>

// ---------------- scratch (static device globals: no allocs) ----------------
__device__ float g_T[2][32][65 * 64];                  // affine-map tree buffers
__device__ __align__(128) __nv_bfloat16 g_Whi[64 * 64]; // pre-swizzled smem image
__device__ __align__(128) __nv_bfloat16 g_Wlo[64 * 64];
__device__ float g_c[64];

// ---------------- helpers ----------------
static __device__ __forceinline__ uint32_t s2u(const void* p) {
    uint32_t a;
    asm("{ .reg .u64 t; cvta.to.shared.u64 t, %1; cvt.u32.u64 %0, t; }"
        : "=r"(a) : "l"(p));
    return a;
}

static __device__ __forceinline__ void ldsm4(uint32_t& r0, uint32_t& r1,
                                             uint32_t& r2, uint32_t& r3, uint32_t a) {
    asm volatile("ldmatrix.sync.aligned.m8n8.x4.shared.b16 {%0,%1,%2,%3}, [%4];"
                 : "=r"(r0), "=r"(r1), "=r"(r2), "=r"(r3) : "r"(a));
}

static __device__ __forceinline__ void mma16816(float* c, const uint32_t* a,
                                                uint32_t b0, uint32_t b1) {
    asm volatile("mma.sync.aligned.m16n8k16.row.col.f32.bf16.bf16.f32 "
                 "{%0,%1,%2,%3}, {%4,%5,%6,%7}, {%8,%9}, {%0,%1,%2,%3};"
                 : "+f"(c[0]), "+f"(c[1]), "+f"(c[2]), "+f"(c[3])
                 : "r"(a[0]), "r"(a[1]), "r"(a[2]), "r"(a[3]), "r"(b0), "r"(b1));
}

// split (a,b) fp32 pair -> packed bf16x2 hi + packed bf16x2 lo (exact residual)
static __device__ __forceinline__ void split2(float a, float b, uint32_t& hi, uint32_t& lo) {
    uint32_t h, l;
    asm("cvt.rn.bf16x2.f32 %0, %1, %2;" : "=r"(h) : "f"(b), "f"(a));
    float ha = __uint_as_float(h << 16);
    float hb = __uint_as_float(h & 0xFFFF0000u);
    float la = a - ha;
    float lb = b - hb;
    asm("cvt.rn.bf16x2.f32 %0, %1, %2;" : "=r"(l) : "f"(lb), "f"(la));
    hi = h; lo = l;
}

// ============================================================================
// Kernel A: init per-layer affine maps. T[l] rows 0..63 = W_l^T, row 64 = b_l.
// ============================================================================
__global__ void __launch_bounds__(256)
init_T(const float* __restrict__ W, const float* __restrict__ Bv)
{
    const int l = blockIdx.x;
    float* D = g_T[0][l];
    for (int idx = threadIdx.x; idx < 65 * 64; idx += 256) {
        const int k = idx >> 6, n = idx & 63;
        D[idx] = (k < 64) ? W[(size_t)l * 4096 + n * 64 + k]
                          : Bv[(size_t)l * 64 + n];
    }
}

// ============================================================================
// Kernel B: one tree level. dst[i] = src[2i] then src[2i+1]; odd tail copies.
// ============================================================================
__global__ void __launch_bounds__(256, 2)
compose(int srcbuf, int n)
{
    __shared__ float Ps[65][68];
    __shared__ float Qs[65][68];

    const int i = blockIdx.x;
    const int tid = threadIdx.x;
    const float* S0 = g_T[srcbuf][2 * i];
    float* D = g_T[srcbuf ^ 1][i];

    if (2 * i + 1 >= n) {                 // odd tail: pass through
        for (int idx = tid; idx < 65 * 64; idx += 256) D[idx] = S0[idx];
        return;
    }
    const float* S1 = g_T[srcbuf][2 * i + 1];

    for (int idx = tid; idx < 65 * 64; idx += 256) {
        Ps[idx >> 6][idx & 63] = S0[idx];
        Qs[idx >> 6][idx & 63] = S1[idx];
    }
    __syncthreads();

    const int r  = tid >> 2;
    const int c0 = (tid & 3) * 16;
    float acc[16];
#pragma unroll
    for (int j = 0; j < 16; j++) acc[j] = 0.f;

#pragma unroll 4
    for (int k = 0; k < 64; k++) {
        const float p = Ps[r][k];
        const float4* q = (const float4*)&Qs[k][c0];
        float4 q0 = q[0], q1 = q[1], q2 = q[2], q3 = q[3];
        acc[0]  += p * q0.x; acc[1]  += p * q0.y; acc[2]  += p * q0.z; acc[3]  += p * q0.w;
        acc[4]  += p * q1.x; acc[5]  += p * q1.y; acc[6]  += p * q1.z; acc[7]  += p * q1.w;
        acc[8]  += p * q2.x; acc[9]  += p * q2.y; acc[10] += p * q2.z; acc[11] += p * q2.w;
        acc[12] += p * q3.x; acc[13] += p * q3.y; acc[14] += p * q3.z; acc[15] += p * q3.w;
    }
#pragma unroll
    for (int j = 0; j < 16; j++) D[r * 64 + c0 + j] = acc[j];

    if (tid < 64) {                        // bias row: Pb·Q.M + Qb
        float a = Qs[64][tid];
#pragma unroll 4
        for (int k = 0; k < 64; k++) a += Ps[64][k] * Qs[k][tid];
        D[64 * 64 + tid] = a;
    }
}

// ============================================================================
// Kernel C: build pre-split, pre-swizzled bf16 weight images + bias.
// Weff[n][k] = Tfinal.M[k][n]; image layout identical to apply's smem ldmatrix view.
// ============================================================================
__global__ void __launch_bounds__(256)
build_eff(int fbuf)
{
    const float* T = g_T[fbuf][0];
    const int tid = threadIdx.x;
    const int wn = tid >> 2;
    const int wk = (tid & 3) * 16;

    float f[16];
#pragma unroll
    for (int j = 0; j < 16; j++) f[j] = T[(wk + j) * 64 + wn];

    uint32_t hi[8], lo[8];
#pragma unroll
    for (int j = 0; j < 8; j++) split2(f[2 * j], f[2 * j + 1], hi[j], lo[j]);

    const uint32_t wxor  = ((uint32_t)(wn & 7)) << 4;
    const uint32_t woff0 = (uint32_t)wn * 128 + (uint32_t)(tid & 3) * 32;
    const uint32_t wsw0  = woff0 ^ wxor;
    const uint32_t wsw1  = (woff0 + 16) ^ wxor;

    *(uint4*)((char*)g_Whi + wsw0) = make_uint4(hi[0], hi[1], hi[2], hi[3]);
    *(uint4*)((char*)g_Whi + wsw1) = make_uint4(hi[4], hi[5], hi[6], hi[7]);
    *(uint4*)((char*)g_Wlo + wsw0) = make_uint4(lo[0], lo[1], lo[2], lo[3]);
    *(uint4*)((char*)g_Wlo + wsw1) = make_uint4(lo[4], lo[5], lo[6], lo[7]);

    if (tid < 64) g_c[tid] = T[64 * 64 + tid];
}

// ============================================================================
// Kernel D: y = x @ Weff^T + c.  256 tokens/CTA, 2 m-tiles/warp, occ 2.
// ============================================================================
__global__ void __launch_bounds__(256, 2)
apply_affine(const float* __restrict__ x, float* __restrict__ out)
{
    __shared__ __align__(128) __nv_bfloat16 Whi[64 * 64];
    __shared__ __align__(128) __nv_bfloat16 Wlo[64 * 64];
    __shared__ float biasS[64];

    const int tid  = threadIdx.x;
    const int lane = tid & 31;
    const int warp = tid >> 5;
    const int gid  = lane >> 2;
    const int tig  = lane & 3;

    const size_t tok0 = (size_t)blockIdx.x * 256 + (size_t)warp * 32 + gid;

    // tile-0 activation loads (issue immediately)
    float2 v0[16];
    {
        const float* p = x + tok0 * 64 + 2 * tig;
#pragma unroll
        for (int kt = 0; kt < 4; kt++) {
            v0[4*kt+0] = *(const float2*)(p + kt * 16);
            v0[4*kt+1] = *(const float2*)(p + kt * 16 + 8 * 64);
            v0[4*kt+2] = *(const float2*)(p + kt * 16 + 8);
            v0[4*kt+3] = *(const float2*)(p + kt * 16 + 8 * 64 + 8);
        }
    }

    // coalesced weight-image copy (2x uint4 per array per thread)
    {
        const uint4* sh = (const uint4*)g_Whi;
        const uint4* sl = (const uint4*)g_Wlo;
        uint4* dh = (uint4*)Whi;
        uint4* dl = (uint4*)Wlo;
        dh[tid] = sh[tid]; dh[tid + 256] = sh[tid + 256];
        dl[tid] = sl[tid]; dl[tid + 256] = sl[tid + 256];
        if (tid < 64) biasS[tid] = g_c[tid];
    }
    __syncthreads();

    // tile-1 loads: in flight while tile-0 computes
    float2 v1[16];
    {
        const float* p = x + (tok0 + 16) * 64 + 2 * tig;
#pragma unroll
        for (int kt = 0; kt < 4; kt++) {
            v1[4*kt+0] = *(const float2*)(p + kt * 16);
            v1[4*kt+1] = *(const float2*)(p + kt * 16 + 8 * 64);
            v1[4*kt+2] = *(const float2*)(p + kt * 16 + 8);
            v1[4*kt+3] = *(const float2*)(p + kt * 16 + 8 * 64 + 8);
        }
    }

    const uint32_t rowoff = (uint32_t)(lane & 15) * 128;
    uint32_t kx[4];
#pragma unroll
    for (int kt = 0; kt < 4; kt++)
        kx[kt] = ((uint32_t)(kt * 32 + ((lane >> 4) << 4))) ^ ((uint32_t)(lane & 7) << 4);
    const uint32_t hBase = s2u(&Whi[0]) + rowoff;
    const uint32_t lBase = s2u(&Wlo[0]) + rowoff;

    float2 bb[8];
#pragma unroll
    for (int nt = 0; nt < 8; nt++)
        bb[nt] = *(const float2*)&biasS[nt * 8 + 2 * tig];

#pragma unroll
    for (int mt = 0; mt < 2; mt++) {
        const float2* v = (mt == 0) ? v0 : v1;

        uint32_t Ahi[4][4], Alo[4][4];
#pragma unroll
        for (int kt = 0; kt < 4; kt++) {
            split2(v[4*kt+0].x, v[4*kt+0].y, Ahi[kt][0], Alo[kt][0]);
            split2(v[4*kt+1].x, v[4*kt+1].y, Ahi[kt][1], Alo[kt][1]);
            split2(v[4*kt+2].x, v[4*kt+2].y, Ahi[kt][2], Alo[kt][2]);
            split2(v[4*kt+3].x, v[4*kt+3].y, Ahi[kt][3], Alo[kt][3]);
        }

        float C[8][4];
#pragma unroll
        for (int nt = 0; nt < 8; nt++)
#pragma unroll
            for (int i = 0; i < 4; i++) C[nt][i] = 0.f;

#pragma unroll
        for (int kt = 0; kt < 4; kt++) {
#pragma unroll
            for (int np = 0; np < 4; np++) {
                uint32_t b0, b1, b2, b3;
                ldsm4(b0, b1, b2, b3, hBase + np * 2048 + kx[kt]);
                mma16816(C[2*np],   Ahi[kt], b0, b2);
                mma16816(C[2*np+1], Ahi[kt], b1, b3);
                mma16816(C[2*np],   Alo[kt], b0, b2);
                mma16816(C[2*np+1], Alo[kt], b1, b3);
                uint32_t q0, q1, q2, q3;
                ldsm4(q0, q1, q2, q3, lBase + np * 2048 + kx[kt]);
                mma16816(C[2*np],   Ahi[kt], q0, q2);
                mma16816(C[2*np+1], Ahi[kt], q1, q3);
            }
        }

        const size_t r = tok0 + mt * 16;
#pragma unroll
        for (int nt = 0; nt < 8; nt++) {
            const int col = nt * 8 + 2 * tig;
            *(float2*)(out + r * 64 + col) =
                make_float2(C[nt][0] + bb[nt].x, C[nt][1] + bb[nt].y);
            *(float2*)(out + (r + 8) * 64 + col) =
                make_float2(C[nt][2] + bb[nt].x, C[nt][3] + bb[nt].y);
        }
    }
}

extern "C" void kernel_launch(void* const* d_in, const int* in_sizes, int n_in,
                              void* d_out, int out_size)
{
    const float* x  = (const float*)d_in[0];
    const float* W  = (const float*)d_in[1];
    const float* Bv = (const float*)d_in[2];
    float* out = (float*)d_out;

    const int ntok = in_sizes[0] / 64;        // 524288
    const int nl   = in_sizes[1] / (64 * 64); // 20

    init_T<<<nl, 256>>>(W, Bv);

    int n = nl, buf = 0;
    while (n > 1) {
        const int np = (n + 1) / 2;
        compose<<<np, 256>>>(buf, n);
        buf ^= 1;
        n = np;
    }

    build_eff<<<1, 256>>>(buf);
    apply_affine<<<ntok / 256, 256>>>(x, out);
}

// round 9
// speedup vs baseline: 19.2175x; 1.1552x over previous
#include <cuda_runtime.h>
#include <cuda_bf16.h>
#include <cstdint>

typedef unsigned long long u64;

// ---------------- scratch (static device globals: no allocs) ----------------
__device__ float g_part[8][65 * 64];                    // partial affine maps
__device__ __align__(128) __nv_bfloat16 g_Whi[64 * 64]; // pre-swizzled smem image
__device__ __align__(128) __nv_bfloat16 g_Wlo[64 * 64];
__device__ float g_c[64];

// ---------------- helpers ----------------
static __device__ __forceinline__ uint32_t s2u(const void* p) {
    uint32_t a;
    asm("{ .reg .u64 t; cvta.to.shared.u64 t, %1; cvt.u32.u64 %0, t; }"
        : "=r"(a) : "l"(p));
    return a;
}

static __device__ __forceinline__ void ldsm4(uint32_t& r0, uint32_t& r1,
                                             uint32_t& r2, uint32_t& r3, uint32_t a) {
    asm volatile("ldmatrix.sync.aligned.m8n8.x4.shared.b16 {%0,%1,%2,%3}, [%4];"
                 : "=r"(r0), "=r"(r1), "=r"(r2), "=r"(r3) : "r"(a));
}

static __device__ __forceinline__ void mma16816(float* c, const uint32_t* a,
                                                uint32_t b0, uint32_t b1) {
    asm volatile("mma.sync.aligned.m16n8k16.row.col.f32.bf16.bf16.f32 "
                 "{%0,%1,%2,%3}, {%4,%5,%6,%7}, {%8,%9}, {%0,%1,%2,%3};"
                 : "+f"(c[0]), "+f"(c[1]), "+f"(c[2]), "+f"(c[3])
                 : "r"(a[0]), "r"(a[1]), "r"(a[2]), "r"(a[3]), "r"(b0), "r"(b1));
}

static __device__ __forceinline__ void split2(float a, float b, uint32_t& hi, uint32_t& lo) {
    uint32_t h, l;
    asm("cvt.rn.bf16x2.f32 %0, %1, %2;" : "=r"(h) : "f"(b), "f"(a));
    float ha = __uint_as_float(h << 16);
    float hb = __uint_as_float(h & 0xFFFF0000u);
    float la = a - ha;
    float lb = b - hb;
    asm("cvt.rn.bf16x2.f32 %0, %1, %2;" : "=r"(l) : "f"(lb), "f"(la));
    hi = h; lo = l;
}

static __device__ __forceinline__ u64 ffma2(u64 a, u64 b, u64 c) {
    u64 d;
    asm("fma.rn.f32x2 %0, %1, %2, %3;" : "=l"(d) : "l"(a), "l"(b), "l"(c));
    return d;
}
static __device__ __forceinline__ u64 splat2(float x) {
    u64 r;
    asm("mov.b64 %0, {%1, %1};" : "=l"(r) : "f"(x));
    return r;
}
static __device__ __forceinline__ void unpack2(u64 v, float& lo, float& hi) {
    asm("mov.b64 {%0, %1}, %2;" : "=f"(lo), "=f"(hi) : "l"(v));
}

// Ps (65x68, rows 0-63 = M, row 64 = bias) := Ps ∘ (Qs, qb); f32x2-packed.
static __device__ __forceinline__ void compose_step(
    float (*Ps)[68], float (*Qs)[68], const float* qb, int tid)
{
    const int r  = tid >> 2;
    const int c0 = (tid & 3) * 16;

    u64 acc[8];
#pragma unroll
    for (int i = 0; i < 8; i++) acc[i] = 0ull;

#pragma unroll 16
    for (int k = 0; k < 64; k++) {
        const u64 p2 = splat2(Ps[r][k]);
        const ulonglong2* q = (const ulonglong2*)&Qs[k][c0];
        ulonglong2 q0 = q[0], q1 = q[1], q2 = q[2], q3 = q[3];
        acc[0] = ffma2(p2, q0.x, acc[0]); acc[1] = ffma2(p2, q0.y, acc[1]);
        acc[2] = ffma2(p2, q1.x, acc[2]); acc[3] = ffma2(p2, q1.y, acc[3]);
        acc[4] = ffma2(p2, q2.x, acc[4]); acc[5] = ffma2(p2, q2.y, acc[5]);
        acc[6] = ffma2(p2, q3.x, acc[6]); acc[7] = ffma2(p2, q3.y, acc[7]);
    }

    float bacc = 0.f;
    if (tid < 64) {
#pragma unroll 8
        for (int k = 0; k < 64; k++) bacc += Ps[64][k] * Qs[k][tid];
        bacc += qb[tid];
    }
    __syncthreads();

    float o[16];
#pragma unroll
    for (int j = 0; j < 8; j++) unpack2(acc[j], o[2 * j], o[2 * j + 1]);
#pragma unroll
    for (int j = 0; j < 16; j++) Ps[r][c0 + j] = o[j];
    if (tid < 64) Ps[64][tid] = bacc;
    __syncthreads();
}

// ============================================================================
// Kernel 1: each CTA composes 4 consecutive layers -> g_part[blockIdx.x].
// Layer l as affine map: M = W_l^T (Ps[k][n] = W[l][n][k]), bias row = b_l.
// ============================================================================
__global__ void __launch_bounds__(256, 1)
prep_part(const float* __restrict__ W, const float* __restrict__ Bv, int nl)
{
    __shared__ __align__(16) float Ps[65][68];
    __shared__ __align__(16) float Qs[64][68];
    __shared__ float qb[64];

    const int tid = threadIdx.x;
    const int l0  = blockIdx.x * 4;
    const int lcnt = (nl - l0 < 4) ? (nl - l0) : 4;

    const int n  = tid >> 2;
    const int kc = (tid & 3) * 16;

    // init Ps = T_{l0}
    {
        const float4* src = (const float4*)(W + (size_t)l0 * 4096 + n * 64 + kc);
        float4 v0 = src[0], v1 = src[1], v2 = src[2], v3 = src[3];
        float f[16] = { v0.x, v0.y, v0.z, v0.w,  v1.x, v1.y, v1.z, v1.w,
                        v2.x, v2.y, v2.z, v2.w,  v3.x, v3.y, v3.z, v3.w };
#pragma unroll
        for (int j = 0; j < 16; j++) Ps[kc + j][n] = f[j];
        if (tid < 64) Ps[64][tid] = Bv[(size_t)l0 * 64 + tid];
    }
    __syncthreads();

    for (int li = 1; li < lcnt; li++) {
        const size_t l = (size_t)(l0 + li);
        const float4* src = (const float4*)(W + l * 4096 + n * 64 + kc);
        float4 v0 = src[0], v1 = src[1], v2 = src[2], v3 = src[3];
        float f[16] = { v0.x, v0.y, v0.z, v0.w,  v1.x, v1.y, v1.z, v1.w,
                        v2.x, v2.y, v2.z, v2.w,  v3.x, v3.y, v3.z, v3.w };
#pragma unroll
        for (int j = 0; j < 16; j++) Qs[kc + j][n] = f[j];
        if (tid < 64) qb[tid] = Bv[l * 64 + tid];
        __syncthreads();
        compose_step(Ps, Qs, qb, tid);
    }

    float* D = g_part[blockIdx.x];
    for (int idx = tid; idx < 65 * 64; idx += 256)
        D[idx] = Ps[idx >> 6][idx & 63];
}

// ============================================================================
// Kernel 2: fold the partials, then emit pre-split/pre-swizzled bf16 images.
// ============================================================================
__global__ void __launch_bounds__(256, 1)
prep_final(int npart)
{
    __shared__ __align__(16) float Ps[65][68];
    __shared__ __align__(16) float Qs[64][68];
    __shared__ float qb[64];

    const int tid = threadIdx.x;

    for (int idx = tid; idx < 65 * 64; idx += 256)
        Ps[idx >> 6][idx & 63] = g_part[0][idx];
    __syncthreads();

    for (int i = 1; i < npart; i++) {
        const float* S = g_part[i];
        for (int idx = tid; idx < 64 * 64; idx += 256)
            Qs[idx >> 6][idx & 63] = S[idx];
        if (tid < 64) qb[tid] = S[64 * 64 + tid];
        __syncthreads();
        compose_step(Ps, Qs, qb, tid);
    }

    // fused build_eff: Weff[n][k] = Ps[k][n] -> bf16 hi/lo SW128 images
    const int wn = tid >> 2;
    const int wk = (tid & 3) * 16;

    float f[16];
#pragma unroll
    for (int j = 0; j < 16; j++) f[j] = Ps[wk + j][wn];

    uint32_t hi[8], lo[8];
#pragma unroll
    for (int j = 0; j < 8; j++) split2(f[2 * j], f[2 * j + 1], hi[j], lo[j]);

    const uint32_t wxor  = ((uint32_t)(wn & 7)) << 4;
    const uint32_t woff0 = (uint32_t)wn * 128 + (uint32_t)(tid & 3) * 32;
    const uint32_t wsw0  = woff0 ^ wxor;
    const uint32_t wsw1  = (woff0 + 16) ^ wxor;

    *(uint4*)((char*)g_Whi + wsw0) = make_uint4(hi[0], hi[1], hi[2], hi[3]);
    *(uint4*)((char*)g_Whi + wsw1) = make_uint4(hi[4], hi[5], hi[6], hi[7]);
    *(uint4*)((char*)g_Wlo + wsw0) = make_uint4(lo[0], lo[1], lo[2], lo[3]);
    *(uint4*)((char*)g_Wlo + wsw1) = make_uint4(lo[4], lo[5], lo[6], lo[7]);

    if (tid < 64) g_c[tid] = Ps[64][tid];
}

// ============================================================================
// Kernel 3: y = x @ Weff^T + c.  256 tokens/CTA, 2 m-tiles/warp, occ 2.
// ============================================================================
__global__ void __launch_bounds__(256, 2)
apply_affine(const float* __restrict__ x, float* __restrict__ out)
{
    __shared__ __align__(128) __nv_bfloat16 Whi[64 * 64];
    __shared__ __align__(128) __nv_bfloat16 Wlo[64 * 64];
    __shared__ float biasS[64];

    const int tid  = threadIdx.x;
    const int lane = tid & 31;
    const int warp = tid >> 5;
    const int gid  = lane >> 2;
    const int tig  = lane & 3;

    const size_t tok0 = (size_t)blockIdx.x * 256 + (size_t)warp * 32 + gid;

    // tile-0 activation loads (issue immediately)
    float2 v0[16];
    {
        const float* p = x + tok0 * 64 + 2 * tig;
#pragma unroll
        for (int kt = 0; kt < 4; kt++) {
            v0[4*kt+0] = *(const float2*)(p + kt * 16);
            v0[4*kt+1] = *(const float2*)(p + kt * 16 + 8 * 64);
            v0[4*kt+2] = *(const float2*)(p + kt * 16 + 8);
            v0[4*kt+3] = *(const float2*)(p + kt * 16 + 8 * 64 + 8);
        }
    }

    // coalesced weight-image copy
    {
        const uint4* sh = (const uint4*)g_Whi;
        const uint4* sl = (const uint4*)g_Wlo;
        uint4* dh = (uint4*)Whi;
        uint4* dl = (uint4*)Wlo;
        dh[tid] = sh[tid]; dh[tid + 256] = sh[tid + 256];
        dl[tid] = sl[tid]; dl[tid + 256] = sl[tid + 256];
        if (tid < 64) biasS[tid] = g_c[tid];
    }
    __syncthreads();

    // tile-1 loads: in flight while tile-0 computes
    float2 v1[16];
    {
        const float* p = x + (tok0 + 16) * 64 + 2 * tig;
#pragma unroll
        for (int kt = 0; kt < 4; kt++) {
            v1[4*kt+0] = *(const float2*)(p + kt * 16);
            v1[4*kt+1] = *(const float2*)(p + kt * 16 + 8 * 64);
            v1[4*kt+2] = *(const float2*)(p + kt * 16 + 8);
            v1[4*kt+3] = *(const float2*)(p + kt * 16 + 8 * 64 + 8);
        }
    }

    const uint32_t rowoff = (uint32_t)(lane & 15) * 128;
    uint32_t kx[4];
#pragma unroll
    for (int kt = 0; kt < 4; kt++)
        kx[kt] = ((uint32_t)(kt * 32 + ((lane >> 4) << 4))) ^ ((uint32_t)(lane & 7) << 4);
    const uint32_t hBase = s2u(&Whi[0]) + rowoff;
    const uint32_t lBase = s2u(&Wlo[0]) + rowoff;

    float2 bb[8];
#pragma unroll
    for (int nt = 0; nt < 8; nt++)
        bb[nt] = *(const float2*)&biasS[nt * 8 + 2 * tig];

#pragma unroll
    for (int mt = 0; mt < 2; mt++) {
        const float2* v = (mt == 0) ? v0 : v1;

        uint32_t Ahi[4][4], Alo[4][4];
#pragma unroll
        for (int kt = 0; kt < 4; kt++) {
            split2(v[4*kt+0].x, v[4*kt+0].y, Ahi[kt][0], Alo[kt][0]);
            split2(v[4*kt+1].x, v[4*kt+1].y, Ahi[kt][1], Alo[kt][1]);
            split2(v[4*kt+2].x, v[4*kt+2].y, Ahi[kt][2], Alo[kt][2]);
            split2(v[4*kt+3].x, v[4*kt+3].y, Ahi[kt][3], Alo[kt][3]);
        }

        float C[8][4];
#pragma unroll
        for (int nt = 0; nt < 8; nt++)
#pragma unroll
            for (int i = 0; i < 4; i++) C[nt][i] = 0.f;

#pragma unroll
        for (int kt = 0; kt < 4; kt++) {
#pragma unroll
            for (int np = 0; np < 4; np++) {
                uint32_t b0, b1, b2, b3;
                ldsm4(b0, b1, b2, b3, hBase + np * 2048 + kx[kt]);
                mma16816(C[2*np],   Ahi[kt], b0, b2);
                mma16816(C[2*np+1], Ahi[kt], b1, b3);
                mma16816(C[2*np],   Alo[kt], b0, b2);
                mma16816(C[2*np+1], Alo[kt], b1, b3);
                uint32_t q0, q1, q2, q3;
                ldsm4(q0, q1, q2, q3, lBase + np * 2048 + kx[kt]);
                mma16816(C[2*np],   Ahi[kt], q0, q2);
                mma16816(C[2*np+1], Ahi[kt], q1, q3);
            }
        }

        const size_t r = tok0 + mt * 16;
#pragma unroll
        for (int nt = 0; nt < 8; nt++) {
            const int col = nt * 8 + 2 * tig;
            *(float2*)(out + r * 64 + col) =
                make_float2(C[nt][0] + bb[nt].x, C[nt][1] + bb[nt].y);
            *(float2*)(out + (r + 8) * 64 + col) =
                make_float2(C[nt][2] + bb[nt].x, C[nt][3] + bb[nt].y);
        }
    }
}

extern "C" void kernel_launch(void* const* d_in, const int* in_sizes, int n_in,
                              void* d_out, int out_size)
{
    const float* x  = (const float*)d_in[0];
    const float* W  = (const float*)d_in[1];
    const float* Bv = (const float*)d_in[2];
    float* out = (float*)d_out;

    const int ntok = in_sizes[0] / 64;        // 524288
    const int nl   = in_sizes[1] / (64 * 64); // 20
    const int npart = (nl + 3) / 4;           // 5

    prep_part<<<npart, 256>>>(W, Bv, nl);
    prep_final<<<1, 256>>>(npart);
    apply_affine<<<ntok / 256, 256>>>(x, out);
}

// round 13
// speedup vs baseline: 30.4028x; 1.5820x over previous
#include <cuda_runtime.h>
#include <cuda_bf16.h>
#include <cstdint>

typedef unsigned long long u64;

// ---------------- scratch (static device globals: no allocs) ----------------
__device__ float g_part[8][65 * 64];                    // partial affine maps
__device__ __align__(128) __nv_bfloat16 g_Whi[64 * 64]; // pre-swizzled smem image
__device__ __align__(128) __nv_bfloat16 g_Wlo[64 * 64];
__device__ float g_c[64];
__device__ int g_flag = 0;                              // worker-completion count

// ---------------- helpers ----------------
static __device__ __forceinline__ uint32_t s2u(const void* p) {
    uint32_t a;
    asm("{ .reg .u64 t; cvta.to.shared.u64 t, %1; cvt.u32.u64 %0, t; }"
        : "=r"(a) : "l"(p));
    return a;
}

static __device__ __forceinline__ void ldsm4(uint32_t& r0, uint32_t& r1,
                                             uint32_t& r2, uint32_t& r3, uint32_t a) {
    asm volatile("ldmatrix.sync.aligned.m8n8.x4.shared.b16 {%0,%1,%2,%3}, [%4];"
                 : "=r"(r0), "=r"(r1), "=r"(r2), "=r"(r3) : "r"(a));
}

static __device__ __forceinline__ void mma16816(float* c, const uint32_t* a,
                                                uint32_t b0, uint32_t b1) {
    asm volatile("mma.sync.aligned.m16n8k16.row.col.f32.bf16.bf16.f32 "
                 "{%0,%1,%2,%3}, {%4,%5,%6,%7}, {%8,%9}, {%0,%1,%2,%3};"
                 : "+f"(c[0]), "+f"(c[1]), "+f"(c[2]), "+f"(c[3])
                 : "r"(a[0]), "r"(a[1]), "r"(a[2]), "r"(a[3]), "r"(b0), "r"(b1));
}

static __device__ __forceinline__ void split2(float a, float b, uint32_t& hi, uint32_t& lo) {
    uint32_t h, l;
    asm("cvt.rn.bf16x2.f32 %0, %1, %2;" : "=r"(h) : "f"(b), "f"(a));
    float ha = __uint_as_float(h << 16);
    float hb = __uint_as_float(h & 0xFFFF0000u);
    float la = a - ha;
    float lb = b - hb;
    asm("cvt.rn.bf16x2.f32 %0, %1, %2;" : "=r"(l) : "f"(lb), "f"(la));
    hi = h; lo = l;
}

static __device__ __forceinline__ u64 ffma2(u64 a, u64 b, u64 c) {
    u64 d;
    asm("fma.rn.f32x2 %0, %1, %2, %3;" : "=l"(d) : "l"(a), "l"(b), "l"(c));
    return d;
}
static __device__ __forceinline__ u64 splat2(float x) {
    u64 r;
    asm("mov.b64 %0, {%1, %1};" : "=l"(r) : "f"(x));
    return r;
}
static __device__ __forceinline__ void unpack2(u64 v, float& lo, float& hi) {
    asm("mov.b64 {%0, %1}, %2;" : "=f"(lo), "=f"(hi) : "l"(v));
}

// Ps (65x68, rows 0-63 = M, row 64 = bias) := Ps ∘ (Qs, qb).
// Register-blocked 4x4: thread (rg, cg) owns rows rg*4..+3, cols cg*4..+3.
// P loads are float4 along k (contiguous); Q loads one ulonglong2 per k.
static __device__ __forceinline__ void compose_fast(
    float (*Ps)[68], float (*Qs)[68], const float* qb, int tid)
{
    const int r0 = (tid >> 4) * 4;
    const int c0 = (tid & 15) * 4;

    u64 acc[4][2];
#pragma unroll
    for (int i = 0; i < 4; i++) { acc[i][0] = 0ull; acc[i][1] = 0ull; }

#pragma unroll 4
    for (int k4 = 0; k4 < 64; k4 += 4) {
        float4 P[4];
#pragma unroll
        for (int i = 0; i < 4; i++)
            P[i] = *(const float4*)&Ps[r0 + i][k4];
#pragma unroll
        for (int j = 0; j < 4; j++) {
            ulonglong2 qq = *(const ulonglong2*)&Qs[k4 + j][c0];
#pragma unroll
            for (int i = 0; i < 4; i++) {
                const float pij = (j == 0) ? P[i].x : (j == 1) ? P[i].y
                                 : (j == 2) ? P[i].z : P[i].w;
                const u64 ps = splat2(pij);
                acc[i][0] = ffma2(ps, qq.x, acc[i][0]);
                acc[i][1] = ffma2(ps, qq.y, acc[i][1]);
            }
        }
    }

    float bacc = 0.f;
    if (tid < 64) {
#pragma unroll 8
        for (int k = 0; k < 64; k++) bacc += Ps[64][k] * Qs[k][tid];
        bacc += qb[tid];
    }
    __syncthreads();

#pragma unroll
    for (int i = 0; i < 4; i++) {
        float a0, a1, a2, a3;
        unpack2(acc[i][0], a0, a1);
        unpack2(acc[i][1], a2, a3);
        *(float4*)&Ps[r0 + i][c0] = make_float4(a0, a1, a2, a3);
    }
    if (tid < 64) Ps[64][tid] = bacc;
    __syncthreads();
}

// ============================================================================
// Kernel 1 (single launch): 5 CTAs compose 4 layers each; workers publish
// partials; CTA 0 folds all partials and emits the bf16/SW128 weight image.
// ============================================================================
__global__ void __launch_bounds__(256, 1)
prep(const float* __restrict__ W, const float* __restrict__ Bv,
     int nl, int npart)
{
    __shared__ __align__(16) float Ps[65][68];
    __shared__ __align__(16) float Qs[64][68];
    __shared__ float qb[64];

    const int tid = threadIdx.x;
    const int cta = blockIdx.x;
    const int l0  = cta * 4;
    const int lcnt = (nl - l0 < 4) ? (nl - l0) : 4;

    const int n  = tid >> 2;
    const int kc = (tid & 3) * 16;

    // ---- phase A: compose lcnt consecutive layers in smem ----
    // init Ps = T_{l0}  (M[k][n] = W[n][k]; transposed store)
    {
        const float4* src = (const float4*)(W + (size_t)l0 * 4096 + n * 64 + kc);
        float4 v0 = src[0], v1 = src[1], v2 = src[2], v3 = src[3];
        float f[16] = { v0.x, v0.y, v0.z, v0.w,  v1.x, v1.y, v1.z, v1.w,
                        v2.x, v2.y, v2.z, v2.w,  v3.x, v3.y, v3.z, v3.w };
#pragma unroll
        for (int j = 0; j < 16; j++) Ps[kc + j][n] = f[j];
        if (tid < 64) Ps[64][tid] = Bv[(size_t)l0 * 64 + tid];
    }

    // stage layer l0+1 into regs
    float fR[16];
    float bR = 0.f;
    if (lcnt > 1) {
        const float4* src = (const float4*)(W + ((size_t)l0 + 1) * 4096 + n * 64 + kc);
        float4 v0 = src[0], v1 = src[1], v2 = src[2], v3 = src[3];
        fR[0]=v0.x; fR[1]=v0.y; fR[2]=v0.z; fR[3]=v0.w;
        fR[4]=v1.x; fR[5]=v1.y; fR[6]=v1.z; fR[7]=v1.w;
        fR[8]=v2.x; fR[9]=v2.y; fR[10]=v2.z; fR[11]=v2.w;
        fR[12]=v3.x; fR[13]=v3.y; fR[14]=v3.z; fR[15]=v3.w;
        if (tid < 64) bR = Bv[((size_t)l0 + 1) * 64 + tid];
    }
    __syncthreads();

    for (int li = 1; li < lcnt; li++) {
        // commit staged layer to Qs/qb
#pragma unroll
        for (int j = 0; j < 16; j++) Qs[kc + j][n] = fR[j];
        if (tid < 64) qb[tid] = bR;

        // prefetch the next layer while composing this one
        if (li + 1 < lcnt) {
            const float4* src = (const float4*)(W + (size_t)(l0 + li + 1) * 4096
                                                  + n * 64 + kc);
            float4 v0 = src[0], v1 = src[1], v2 = src[2], v3 = src[3];
            fR[0]=v0.x; fR[1]=v0.y; fR[2]=v0.z; fR[3]=v0.w;
            fR[4]=v1.x; fR[5]=v1.y; fR[6]=v1.z; fR[7]=v1.w;
            fR[8]=v2.x; fR[9]=v2.y; fR[10]=v2.z; fR[11]=v2.w;
            fR[12]=v3.x; fR[13]=v3.y; fR[14]=v3.z; fR[15]=v3.w;
            if (tid < 64) bR = Bv[(size_t)(l0 + li + 1) * 64 + tid];
        }
        __syncthreads();
        compose_fast(Ps, Qs, qb, tid);
    }

    // ---- phase B: workers publish and exit ----
    if (cta != 0) {
        float* D = g_part[cta];
        for (int idx = tid; idx < 65 * 64; idx += 256)
            D[idx] = Ps[idx >> 6][idx & 63];
        __threadfence();
        __syncthreads();
        if (tid == 0) atomicAdd(&g_flag, 1);
        return;
    }

    // ---- phase C (CTA 0): wait for workers, fold, emit image ----
    if (tid == 0) {
        while (atomicAdd(&g_flag, 0) != npart - 1) { }
        __threadfence();
    }
    __syncthreads();

    for (int i = 1; i < npart; i++) {
        const float* S = g_part[i];
        for (int idx = tid; idx < 64 * 64; idx += 256)
            Qs[idx >> 6][idx & 63] = S[idx];
        if (tid < 64) qb[tid] = S[64 * 64 + tid];
        __syncthreads();
        compose_fast(Ps, Qs, qb, tid);
    }

    // fused build_eff: Weff[n][k] = Ps[k][n] -> bf16 hi/lo SW128 images
    {
        const int wn = tid >> 2;
        const int wk = (tid & 3) * 16;

        float f[16];
#pragma unroll
        for (int j = 0; j < 16; j++) f[j] = Ps[wk + j][wn];

        uint32_t hi[8], lo[8];
#pragma unroll
        for (int j = 0; j < 8; j++) split2(f[2 * j], f[2 * j + 1], hi[j], lo[j]);

        const uint32_t wxor  = ((uint32_t)(wn & 7)) << 4;
        const uint32_t woff0 = (uint32_t)wn * 128 + (uint32_t)(tid & 3) * 32;
        const uint32_t wsw0  = woff0 ^ wxor;
        const uint32_t wsw1  = (woff0 + 16) ^ wxor;

        *(uint4*)((char*)g_Whi + wsw0) = make_uint4(hi[0], hi[1], hi[2], hi[3]);
        *(uint4*)((char*)g_Whi + wsw1) = make_uint4(hi[4], hi[5], hi[6], hi[7]);
        *(uint4*)((char*)g_Wlo + wsw0) = make_uint4(lo[0], lo[1], lo[2], lo[3]);
        *(uint4*)((char*)g_Wlo + wsw1) = make_uint4(lo[4], lo[5], lo[6], lo[7]);

        if (tid < 64) g_c[tid] = Ps[64][tid];
    }

    // reset handoff flag so every graph replay starts clean (deterministic)
    __syncthreads();
    if (tid == 0) atomicExch(&g_flag, 0);
}

// ============================================================================
// Kernel 2: y = x @ Weff^T + c.  256 tokens/CTA, 2 m-tiles/warp, occ 2.
// ============================================================================
__global__ void __launch_bounds__(256, 2)
apply_affine(const float* __restrict__ x, float* __restrict__ out)
{
    __shared__ __align__(128) __nv_bfloat16 Whi[64 * 64];
    __shared__ __align__(128) __nv_bfloat16 Wlo[64 * 64];
    __shared__ float biasS[64];

    const int tid  = threadIdx.x;
    const int lane = tid & 31;
    const int warp = tid >> 5;
    const int gid  = lane >> 2;
    const int tig  = lane & 3;

    const size_t tok0 = (size_t)blockIdx.x * 256 + (size_t)warp * 32 + gid;

    // tile-0 activation loads (issue immediately)
    float2 v0[16];
    {
        const float* p = x + tok0 * 64 + 2 * tig;
#pragma unroll
        for (int kt = 0; kt < 4; kt++) {
            v0[4*kt+0] = *(const float2*)(p + kt * 16);
            v0[4*kt+1] = *(const float2*)(p + kt * 16 + 8 * 64);
            v0[4*kt+2] = *(const float2*)(p + kt * 16 + 8);
            v0[4*kt+3] = *(const float2*)(p + kt * 16 + 8 * 64 + 8);
        }
    }

    // coalesced weight-image copy
    {
        const uint4* sh = (const uint4*)g_Whi;
        const uint4* sl = (const uint4*)g_Wlo;
        uint4* dh = (uint4*)Whi;
        uint4* dl = (uint4*)Wlo;
        dh[tid] = sh[tid]; dh[tid + 256] = sh[tid + 256];
        dl[tid] = sl[tid]; dl[tid + 256] = sl[tid + 256];
        if (tid < 64) biasS[tid] = g_c[tid];
    }
    __syncthreads();

    // tile-1 loads: in flight while tile-0 computes
    float2 v1[16];
    {
        const float* p = x + (tok0 + 16) * 64 + 2 * tig;
#pragma unroll
        for (int kt = 0; kt < 4; kt++) {
            v1[4*kt+0] = *(const float2*)(p + kt * 16);
            v1[4*kt+1] = *(const float2*)(p + kt * 16 + 8 * 64);
            v1[4*kt+2] = *(const float2*)(p + kt * 16 + 8);
            v1[4*kt+3] = *(const float2*)(p + kt * 16 + 8 * 64 + 8);
        }
    }

    const uint32_t rowoff = (uint32_t)(lane & 15) * 128;
    uint32_t kx[4];
#pragma unroll
    for (int kt = 0; kt < 4; kt++)
        kx[kt] = ((uint32_t)(kt * 32 + ((lane >> 4) << 4))) ^ ((uint32_t)(lane & 7) << 4);
    const uint32_t hBase = s2u(&Whi[0]) + rowoff;
    const uint32_t lBase = s2u(&Wlo[0]) + rowoff;

    float2 bb[8];
#pragma unroll
    for (int nt = 0; nt < 8; nt++)
        bb[nt] = *(const float2*)&biasS[nt * 8 + 2 * tig];

#pragma unroll
    for (int mt = 0; mt < 2; mt++) {
        const float2* v = (mt == 0) ? v0 : v1;

        uint32_t Ahi[4][4], Alo[4][4];
#pragma unroll
        for (int kt = 0; kt < 4; kt++) {
            split2(v[4*kt+0].x, v[4*kt+0].y, Ahi[kt][0], Alo[kt][0]);
            split2(v[4*kt+1].x, v[4*kt+1].y, Ahi[kt][1], Alo[kt][1]);
            split2(v[4*kt+2].x, v[4*kt+2].y, Ahi[kt][2], Alo[kt][2]);
            split2(v[4*kt+3].x, v[4*kt+3].y, Ahi[kt][3], Alo[kt][3]);
        }

        float C[8][4];
#pragma unroll
        for (int nt = 0; nt < 8; nt++)
#pragma unroll
            for (int i = 0; i < 4; i++) C[nt][i] = 0.f;

#pragma unroll
        for (int kt = 0; kt < 4; kt++) {
#pragma unroll
            for (int np = 0; np < 4; np++) {
                uint32_t b0, b1, b2, b3;
                ldsm4(b0, b1, b2, b3, hBase + np * 2048 + kx[kt]);
                mma16816(C[2*np],   Ahi[kt], b0, b2);
                mma16816(C[2*np+1], Ahi[kt], b1, b3);
                mma16816(C[2*np],   Alo[kt], b0, b2);
                mma16816(C[2*np+1], Alo[kt], b1, b3);
                uint32_t q0, q1, q2, q3;
                ldsm4(q0, q1, q2, q3, lBase + np * 2048 + kx[kt]);
                mma16816(C[2*np],   Ahi[kt], q0, q2);
                mma16816(C[2*np+1], Ahi[kt], q1, q3);
            }
        }

        const size_t r = tok0 + mt * 16;
#pragma unroll
        for (int nt = 0; nt < 8; nt++) {
            const int col = nt * 8 + 2 * tig;
            *(float2*)(out + r * 64 + col) =
                make_float2(C[nt][0] + bb[nt].x, C[nt][1] + bb[nt].y);
            *(float2*)(out + (r + 8) * 64 + col) =
                make_float2(C[nt][2] + bb[nt].x, C[nt][3] + bb[nt].y);
        }
    }
}

extern "C" void kernel_launch(void* const* d_in, const int* in_sizes, int n_in,
                              void* d_out, int out_size)
{
    const float* x  = (const float*)d_in[0];
    const float* W  = (const float*)d_in[1];
    const float* Bv = (const float*)d_in[2];
    float* out = (float*)d_out;

    const int ntok = in_sizes[0] / 64;        // 524288
    const int nl   = in_sizes[1] / (64 * 64); // 20
    const int npart = (nl + 3) / 4;           // 5

    prep<<<npart, 256>>>(W, Bv, nl, npart);
    apply_affine<<<ntok / 256, 256>>>(x, out);
}